// round 8
// baseline (speedup 1.0000x reference)
#include <cuda_runtime.h>
#include <stdint.h>
#include <math.h>

#define NCAND  1600
#define NITER  100
#define NZ     16
#define NB     65536                // 2^16 bins
#define FRAC   7                    // 7-bit sub-bin offset; NB<<FRAC = 2^23
#define NCHUNK 128
#define CHUNK  (NB / NCHUNK)        // 512
#define GRID   148
#define BLK    1024

#define MAGICF 8388608.0f           // 2^23
#define HIF    16777215.0f          // 2^24 - 1
#define OVF    16777216.0f          // 2^24

typedef unsigned long long u64;
typedef long long          s64;
typedef unsigned           u32;

// ---------------- device scratch ----------------
__device__ u32   g_ctr;
__device__ float g_bmin[GRID], g_bmax[GRID];
__device__ u64   g_hist[NB];        // (count << 32) | sum_of_7bit_offsets
__device__ u32   g_pc[NB + 1];      // chunk-relative exclusive prefix counts
__device__ u64   g_ps[NB + 1];      // chunk-relative exclusive prefix units
__device__ u32   g_ccnt[NCHUNK];
__device__ u64   g_csum[NCHUNK];

__device__ __forceinline__ void gbar_full(u32 k) {
    __syncthreads();
    if (threadIdx.x == 0) {
        __threadfence();
        atomicAdd(&g_ctr, 1u);
        u32 target = k * (u32)GRID;
        while ((int)(*(volatile u32*)&g_ctr - target) < 0) __nanosleep(64);
        __threadfence();
    }
    __syncthreads();
}

__global__ void __launch_bounds__(BLK, 1)
fused_kernel(const float4* __restrict__ x4, int n4, int ntot,
             float* __restrict__ out)
{
    const int tid  = threadIdx.x;
    const int bid  = blockIdx.x;
    const int gtid = bid * BLK + tid;
    const int gsz  = GRID * BLK;

    __shared__ float  s_mn[32], s_mx[32];
    __shared__ float  s_rm[GRID >> 1], s_rx[GRID >> 1];
    __shared__ float  sb_xmin, sb_xmax, sb_C1, sb_C2;
    __shared__ u32    s_c[CHUNK];
    __shared__ u64    s_s[CHUNK];
    __shared__ u32    s_cc[NCHUNK];
    __shared__ u64    s_cs[NCHUNK];
    __shared__ u32    s_cpref[NCHUNK + 1];
    __shared__ u64    s_spref[NCHUNK + 1];
    __shared__ double s_score[NCAND];
    __shared__ float  s_nmin[NCAND], s_nmax[NCAND];
    __shared__ double sm_i[NITER];
    __shared__ int    j_i[NITER];

    // ---------------- P0: clear hist + per-block min/max ----------------
    for (int i = gtid; i < NB; i += gsz) g_hist[i] = 0ull;

    float lmin = 3.4e38f, lmax = -3.4e38f;
    for (int i = gtid; i < n4; i += gsz) {
        float4 v = __ldg(&x4[i]);
        lmin = fminf(lmin, fminf(fminf(v.x, v.y), fminf(v.z, v.w)));
        lmax = fmaxf(lmax, fmaxf(fmaxf(v.x, v.y), fmaxf(v.z, v.w)));
    }
    #pragma unroll
    for (int o = 16; o; o >>= 1) {
        lmin = fminf(lmin, __shfl_xor_sync(0xffffffffu, lmin, o));
        lmax = fmaxf(lmax, __shfl_xor_sync(0xffffffffu, lmax, o));
    }
    if ((tid & 31) == 0) { s_mn[tid >> 5] = lmin; s_mx[tid >> 5] = lmax; }
    __syncthreads();
    if (tid == 0) {
        #pragma unroll
        for (int i = 1; i < 32; i++) {
            lmin = fminf(lmin, s_mn[i]);
            lmax = fmaxf(lmax, s_mx[i]);
        }
        g_bmin[bid] = lmin;
        g_bmax[bid] = lmax;
    }
    gbar_full(1);

    // ---------------- P1: finish min/max, derive magic-bin constants ------
    if (tid < GRID / 2) {
        int j = tid + GRID / 2;
        s_rm[tid] = fminf(__ldcg(&g_bmin[tid]), __ldcg(&g_bmin[j]));
        s_rx[tid] = fmaxf(__ldcg(&g_bmax[tid]), __ldcg(&g_bmax[j]));
    }
    __syncthreads();
    for (int off = GRID / 4; off; off >>= 1) {   // 74 -> ... -> 1 (GRID=148)
        if (tid < off) {
            s_rm[tid] = fminf(s_rm[tid], s_rm[tid + off]);
            s_rx[tid] = fmaxf(s_rx[tid], s_rx[tid + off]);
        }
        __syncthreads();
    }
    if (tid == 0) {
        float xmin = fminf(s_rm[0], s_rm[1]);
        float xmax = fmaxf(s_rx[0], s_rx[1]);
        float xr = xmax - xmin;
        float C1 = MAGICF / xr;                  // 2^23 / range
        sb_xmin = xmin; sb_xmax = xmax;
        sb_C1 = C1;
        sb_C2 = MAGICF - xmin * C1;
    }
    __syncthreads();
    const float C1 = sb_C1;
    const float C2 = sb_C2;

    // ---------------- P1b: histogram, ~6 ops + 1 u64 atomic per element ---
    for (int i = gtid; i < n4; i += gsz) {
        float4 v = __ldg(&x4[i]);
        float f[4] = {v.x, v.y, v.z, v.w};
        #pragma unroll
        for (int k = 0; k < 4; k++) {
            float t = fmaf(f[k], C1, C2);
            t = fminf(fmaxf(t, MAGICF), HIF);
            u32 q = __float_as_uint(t) - 0x4B000000u;   // 23-bit position
            atomicAdd(&g_hist[q >> FRAC],
                      (1ull << 32) + (u64)(q & ((1u << FRAC) - 1u)));
        }
    }
    gbar_full(2);

    // ---------------- P2: chunk scan (chunks 0..127 <-> blocks 0..127) ----
    if (bid < NCHUNK) {
        int i = bid * CHUNK + tid;
        u32 v = 0; u64 w = 0;
        if (tid < CHUNK) {
            u64 p = __ldcg(&g_hist[i]);
            u32 cnt = (u32)(p >> 32);
            v = cnt;
            w = ((u64)cnt * (u64)i << FRAC) + (p & 0xFFFFFFFFull);
            s_c[tid] = v; s_s[tid] = w;
        }
        __syncthreads();
        for (int off = 1; off < CHUNK; off <<= 1) {
            u32 a = 0; u64 a2 = 0;
            if (tid < CHUNK && tid >= off) { a = s_c[tid - off]; a2 = s_s[tid - off]; }
            __syncthreads();
            if (tid < CHUNK) { s_c[tid] += a; s_s[tid] += a2; }
            __syncthreads();
        }
        if (tid < CHUNK) {
            g_pc[i] = s_c[tid] - v;              // chunk-relative exclusive
            g_ps[i] = s_s[tid] - w;
        }
        if (tid == CHUNK - 1) {
            g_ccnt[bid] = s_c[tid];
            g_csum[bid] = s_s[tid];
            if (bid == NCHUNK - 1) { g_pc[NB] = 0u; g_ps[NB] = 0ull; }
        }
    }

    // ---------------- P3 sync: arrive-only for blocks != 0 ----------------
    __syncthreads();
    if (bid != 0) {
        if (tid == 0) { __threadfence(); atomicAdd(&g_ctr, 1u); }
        return;
    }
    if (tid == 0) {
        __threadfence();
        atomicAdd(&g_ctr, 1u);
        while ((int)(*(volatile u32*)&g_ctr - 3u * GRID) < 0) __nanosleep(64);
        __threadfence();
    }
    __syncthreads();

    // ---------------- P4 (block 0): scores + reference-exact select -------
    if (tid < NCHUNK) {
        s_cc[tid] = __ldcg(&g_ccnt[tid]);
        s_cs[tid] = __ldcg(&g_csum[tid]);
    }
    __syncthreads();
    if (tid <= NCHUNK) {
        u32 c = 0; u64 s = 0;
        for (int j = 0; j < tid; j++) { c += s_cc[j]; s += s_cs[j]; }
        s_cpref[tid] = c; s_spref[tid] = s;
    }
    __syncthreads();

    const float x_min = sb_xmin;
    const float x_max = sb_xmax;
    const float xrange = x_max - x_min;
    const double xmind = (double)x_min;
    const double UPQ = (double)xrange / (double)(NB << FRAC);  // x per unit
    const float EPS = 1.1920929e-7f;             // np.finfo(float32).eps

    for (int c = tid; c < NCAND; c += BLK) {
        int ii = c / NZ + 1;
        int z  = c % NZ;
        float fi = (float)ii, fz = (float)z;
        float tmp_max   = xrange / 100.0f * fi;
        float tmp_delta = tmp_max / 15.0f;
        float new_min = fmaxf(-fz * tmp_delta, x_min);
        float new_max = fminf(tmp_max - fz * tmp_delta, x_max);
        float min_neg = fminf(new_min, 0.0f);
        float max_pos = fmaxf(new_max, 0.0f);
        float scale = fmaxf((max_pos - min_neg) / 15.0f, EPS);
        float zp = fminf(fmaxf(0.0f - rintf(min_neg / scale), 0.0f), 15.0f);
        float ql = -zp;
        s_nmin[c] = new_min;
        s_nmax[c] = new_max;

        int e[NZ + 1];
        e[0] = 0; e[NZ] = NB;
        #pragma unroll
        for (int m = 0; m < NZ - 1; m++) {
            float tr = fmaf((ql + (float)m + 0.5f) * scale, C1, C2);
            int ei;
            if (!(tr > MAGICF))      ei = 0;
            else if (tr >= OVF)      ei = NB;
            else ei = (int)((__float_as_uint(tr) - 0x4B000000u) >> FRAC);
            e[m + 1] = ei;
        }
        #pragma unroll
        for (int m = 1; m < NZ; m++) if (e[m] < e[m - 1]) e[m] = e[m - 1];

        double num = 0.0;
        #pragma unroll
        for (int m = 0; m < NZ; m++) {
            int e0 = e[m], e1 = e[m + 1];
            u32 pc0 = s_cpref[e0 >> 9] + __ldcg(&g_pc[e0]);
            u32 pc1 = s_cpref[e1 >> 9] + __ldcg(&g_pc[e1]);
            u64 ps0 = s_spref[e0 >> 9] + __ldcg(&g_ps[e0]);
            u64 ps1 = s_spref[e1 >> 9] + __ldcg(&g_ps[e1]);
            double Nm = (double)(pc1 - pc0);
            double S1 = (double)(s64)(ps1 - ps0) * UPQ + Nm * xmind;
            float a = (ql + (float)m) * scale;
            double ad = (double)a;
            num += ad * ad * Nm - 2.0 * ad * S1;
        }
        s_score[c] = num / (double)ntot;         // Σx² omitted: constant offset
    }
    __syncthreads();

    if (tid < NITER) {
        int j = 0;
        double sm = s_score[tid * NZ];
        #pragma unroll
        for (int z = 1; z < NZ; z++) {
            double s = s_score[tid * NZ + z];
            if (s < sm) { sm = s; j = z; }       // first-occurrence argmin
        }
        sm_i[tid] = sm; j_i[tid] = j;
    }
    __syncthreads();
    if (tid == 0) {
        double best = 1e30;
        float bmin = x_min, bmax = x_max;
        for (int i = 0; i < NITER; i++) {
            if (sm_i[i] < best) {                // strict <, like reference
                best = sm_i[i];
                bmin = s_nmin[i * NZ + j_i[i]];
                bmax = s_nmax[i * NZ + j_i[i]];
            }
        }
        out[0] = bmin;
        out[1] = bmax;
        atomicExch(&g_ctr, 0u);                  // reset for next graph replay
    }
}

extern "C" void kernel_launch(void* const* d_in, const int* in_sizes, int n_in,
                              void* d_out, int out_size) {
    const float* x = (const float*)d_in[0];
    int n = in_sizes[0];
    fused_kernel<<<GRID, BLK>>>((const float4*)x, n / 4, n, (float*)d_out);
}